// round 5
// baseline (speedup 1.0000x reference)
#include <cuda_runtime.h>
#include <cuda_bf16.h>

// DistortionLoss, O(N) via sorted-midpoint prefix sums.
//   s_k = z_k + z_{k+1};  dz_k = z_{k+1} - z_k
//   loss = inv * [ sum_k w_k*(s_k*W_<k - WS_<k) + (1/3)*sum_k w_k^2*dz_k ]
//
// R5: TWO rays per warp. Lanes 0-15 -> ray 2*wid, lanes 16-31 -> ray 2*wid+1,
// 8 elements per lane. Segmented 16-lane scan (4 steps) + segmented butterfly
// reduce (4 steps) replace the 5-step full-warp ladders; warp count halves.
// z loaded as aligned float4s; row misalignment r = ray & 3 is segment-uniform,
// so neighbor-quad shuffles run branchless and a shuffle-free branch selects.

#define FULL 0xFFFFFFFFu

__global__ void __launch_bounds__(256) distortion_loss_kernel(
    const float*  __restrict__ w,     // [R,128]
    const float*  __restrict__ z,     // [R,129]
    const float*  __restrict__ nearp, // [R]
    const float*  __restrict__ farp,  // [R]
    float* __restrict__ out)          // [R]
{
    const int wid  = (blockIdx.x * 256 + threadIdx.x) >> 5;
    const int lane = threadIdx.x & 31;
    const int li   = lane & 15;            // lane within segment
    const int ray  = 2 * wid + (lane >> 4);

    // ---- front-batched loads ----
    const int e0 = ray * 129;
    const int qa = e0 >> 2;                // first aligned quad of the row
    const int r  = e0 & 3;                 // = ray & 3, segment-uniform

    const float4* zq = reinterpret_cast<const float4*>(z);
    const float4 a  = zq[qa + 2 * li];     // row elems [8li-r .. 8li+3-r]
    const float4 b  = zq[qa + 2 * li + 1]; // row elems [8li+4-r .. 8li+7-r]
    const float4 qt = zq[qa + 32];         // tail quad (row elems 128-r .. 131-r)

    const float4* wq = reinterpret_cast<const float4*>(w + (size_t)ray * 128);
    const float4 wA = wq[2 * li];
    const float4 wB = wq[2 * li + 1];

    const float nr = __ldg(nearp + ray);
    const float fr = __ldg(farp  + ray);

    // ---- neighbor's first quad (branchless shuffles, full mask) ----
    float n0 = __shfl_down_sync(FULL, a.x, 1);
    float n1 = __shfl_down_sync(FULL, a.y, 1);
    float n2 = __shfl_down_sync(FULL, a.z, 1);
    float n3 = __shfl_down_sync(FULL, a.w, 1);
    if (li == 15) { n0 = qt.x; n1 = qt.y; n2 = qt.z; n3 = qt.w; }

    // ---- select row elements 8li .. 8li+8 (no shuffles inside branches) ----
    float zv[9];
    if (r == 0) {
        zv[0]=a.x; zv[1]=a.y; zv[2]=a.z; zv[3]=a.w;
        zv[4]=b.x; zv[5]=b.y; zv[6]=b.z; zv[7]=b.w; zv[8]=n0;
    } else if (r == 1) {
        zv[0]=a.y; zv[1]=a.z; zv[2]=a.w;
        zv[3]=b.x; zv[4]=b.y; zv[5]=b.z; zv[6]=b.w; zv[7]=n0; zv[8]=n1;
    } else if (r == 2) {
        zv[0]=a.z; zv[1]=a.w;
        zv[2]=b.x; zv[3]=b.y; zv[4]=b.z; zv[5]=b.w; zv[6]=n0; zv[7]=n1; zv[8]=n2;
    } else {
        zv[0]=a.w;
        zv[1]=b.x; zv[2]=b.y; zv[3]=b.z; zv[4]=b.w; zv[5]=n0; zv[6]=n1; zv[7]=n2; zv[8]=n3;
    }

    float wv[8] = {wA.x, wA.y, wA.z, wA.w, wB.x, wB.y, wB.z, wB.w};

    // s = z_k + z_{k+1};  ws = w*s
    float s[8], ws[8];
    #pragma unroll
    for (int k = 0; k < 8; k++) { s[k] = zv[k] + zv[k + 1]; ws[k] = wv[k] * s[k]; }

    // lane-local inclusive sums
    float cw[8], cws[8];
    cw[0] = wv[0]; cws[0] = ws[0];
    #pragma unroll
    for (int k = 1; k < 8; k++) {
        cw[k]  = cw[k - 1]  + wv[k];
        cws[k] = cws[k - 1] + ws[k];
    }
    const float tw = cw[7], tws = cws[7];

    // segmented 16-lane inclusive scan of lane totals (4 steps)
    float pw = tw, pws = tws;
    #pragma unroll
    for (int off = 1; off < 16; off <<= 1) {
        const float aw  = __shfl_up_sync(FULL, pw,  off);
        const float aws = __shfl_up_sync(FULL, pws, off);
        if (li >= off) { pw += aw; pws += aws; }
    }
    const float bw  = pw  - tw;   // exclusive base over segment lanes < li
    const float bws = pws - tws;

    // pairwise term + (1/3) w^2 dz term
    float acc = wv[0] * fmaf(s[0], bw, -bws);
    #pragma unroll
    for (int k = 1; k < 8; k++)
        acc += wv[k] * fmaf(s[k], bw + cw[k - 1], -(bws + cws[k - 1]));

    float qq = wv[0] * wv[0] * (zv[1] - zv[0]);
    #pragma unroll
    for (int k = 1; k < 8; k++)
        qq += wv[k] * wv[k] * (zv[k + 1] - zv[k]);
    acc = fmaf(qq, (1.0f / 3.0f), acc);

    // segmented butterfly reduction (4 steps, stays within the 16-lane segment)
    #pragma unroll
    for (int off = 8; off > 0; off >>= 1)
        acc += __shfl_xor_sync(FULL, acc, off);

    if (li == 0)
        out[ray] = acc * __fdividef(1.0f, fr - nr);
}

extern "C" void kernel_launch(void* const* d_in, const int* in_sizes, int n_in,
                              void* d_out, int out_size)
{
    const float* w   = (const float*)d_in[0]; // weights [R,128,1]
    const float* z   = (const float*)d_in[1]; // z_vals  [R,129]
    const float* nr  = (const float*)d_in[2]; // near    [R,1]
    const float* fr  = (const float*)d_in[3]; // far     [R,1]
    float*       out = (float*)d_out;         // [R,1]

    const int R = in_sizes[0] / 128;          // 8192
    const int warps  = R / 2;                 // 2 rays per warp
    const int blocks = warps / 8;             // 8 warps per 256-thread block
    distortion_loss_kernel<<<blocks, 256>>>(w, z, nr, fr, out);
}